// round 8
// baseline (speedup 1.0000x reference)
#include <cuda_runtime.h>
#include <cuda_bf16.h>
#include <math.h>

// Problem constants (fixed by the reference setup)
#define BB 4
#define CC 32
#define NCP 16          // channel pairs
#define PP 262144       // 512*512 pixels per image
#define NI 100          // n_instances
#define CHUNK 2048      // pixels per block
#define TPB 512
#define NCOPY 8         // bank-sliced histogram copies
#define CHUNKS_PER_IMG (PP/CHUNK)   // 128
#define NBLK (BB*CHUNKS_PER_IMG)    // 512

// Scratch (no device allocation allowed -> __device__ globals).
// Zero at module load; pass2's ticket block re-zeros everything after each
// run so every graph replay starts clean.
__device__ float g_sums[BB*CC*NI];   // [b][c][k]
__device__ int   g_counts[BB*NI];
__device__ float g_means[BB*CC*NI];  // [b][c*NI+k]
__device__ float g_invc[BB*NI];
__device__ float g_var[BB];
__device__ float g_dist[BB];
__device__ float g_reg[BB];
__device__ unsigned int g_t1;
__device__ unsigned int g_t2;

// -------- Pass 1: per-label sums (bf16x2 atomics, 8-way bank-sliced) --------
// Last block (ticket) additionally computes means, inv-counts, distance and
// reg terms for all batches.
__global__ __launch_bounds__(TPB) void pass1_k(const float* __restrict__ in,
                                               const int* __restrict__ tgt) {
    __shared__ __nv_bfloat162 ssum[NCP*NI*NCOPY];   // [(cp*100+k)*8 + copy]
    __shared__ int scnt[NI];
    __shared__ bool s_last;

    int blk   = blockIdx.x;
    int b     = blk >> 7;           // /128
    int chunk = blk & 127;
    int p0    = chunk * CHUNK;
    int t     = threadIdx.x;
    int cpy   = t & (NCOPY-1);

    __nv_bfloat162 z2 = __nv_bfloat162(__float2bfloat16(0.f), __float2bfloat16(0.f));
    for (int i = t; i < NCP*NI*NCOPY; i += TPB) ssum[i] = z2;
    for (int i = t; i < NI;           i += TPB) scnt[i] = 0;
    __syncthreads();

    const int4* tg = (const int4*)(tgt + (size_t)b * PP + p0);
    int4 lv = tg[t];
    int lbl[4] = {lv.x, lv.y, lv.z, lv.w};
#pragma unroll
    for (int k = 0; k < 4; k++) atomicAdd(&scnt[lbl[k]], 1);

    int s0 = lbl[0]*NCOPY + cpy;
    int s1 = lbl[1]*NCOPY + cpy;
    int s2 = lbl[2]*NCOPY + cpy;
    int s3 = lbl[3]*NCOPY + cpy;

    const float* base = in + (size_t)b * CC * PP + p0;
#pragma unroll 2
    for (int cp = 0; cp < NCP; cp++) {
        const float4* pc0 = (const float4*)(base + (size_t)(2*cp)   * PP);
        const float4* pc1 = (const float4*)(base + (size_t)(2*cp+1) * PP);
        float4 v0 = pc0[t];
        float4 v1 = pc1[t];
        __nv_bfloat162 p0v = __floats2bfloat162_rn(v0.x, v1.x);
        __nv_bfloat162 p1v = __floats2bfloat162_rn(v0.y, v1.y);
        __nv_bfloat162 p2v = __floats2bfloat162_rn(v0.z, v1.z);
        __nv_bfloat162 p3v = __floats2bfloat162_rn(v0.w, v1.w);
        int cb = cp*NI*NCOPY;
        atomicAdd(&ssum[cb + s0], p0v);
        atomicAdd(&ssum[cb + s1], p1v);
        atomicAdd(&ssum[cb + s2], p2v);
        atomicAdd(&ssum[cb + s3], p3v);
    }
    __syncthreads();

    // flush: reduce copies, bf16 -> fp32 global accumulators
    float* gs = g_sums + (size_t)b * CC * NI;
    for (int i = t; i < NCP*NI; i += TPB) {
        int cp = i / NI;
        int k  = i - cp * NI;
        float sx = 0.f, sy = 0.f;
#pragma unroll
        for (int c = 0; c < NCOPY; c++) {
            __nv_bfloat162 v = ssum[i*NCOPY + c];
            sx += __bfloat162float(v.x);
            sy += __bfloat162float(v.y);
        }
        atomicAdd(&gs[(2*cp)   * NI + k], sx);
        atomicAdd(&gs[(2*cp+1) * NI + k], sy);
    }
    int* gc = g_counts + b * NI;
    for (int i = t; i < NI; i += TPB) atomicAdd(&gc[i], scnt[i]);

    // ---- ticket: last block computes means/invc + distance + reg ----
    __syncthreads();
    if (t == 0) {
        __threadfence();
        unsigned r = atomicAdd(&g_t1, 1u);
        s_last = (r == NBLK - 1);
    }
    __syncthreads();
    if (!s_last) return;

    float* sm  = (float*)ssum;              // reuse smem: [k*33+c], 3300 floats
    float* red = sm + NI*33;                // + reduction scratch

    for (int bb = 0; bb < BB; bb++) {
        const float* gsb = g_sums + (size_t)bb * CC * NI;
        const int*   gcb = g_counts + bb * NI;
        __syncthreads();
        for (int i = t; i < CC*NI; i += TPB) {
            int c = i / NI;
            int k = i - c * NI;
            int cnt = gcb[k];
            float m = (cnt > 0) ? gsb[i] / (float)cnt : 0.f;
            g_means[(size_t)bb*CC*NI + i] = m;
            sm[k*33 + c] = m;
        }
        for (int k = t; k < NI; k += TPB) {
            int cnt = gcb[k];
            g_invc[bb*NI + k] = (cnt > 0) ? 1.f / (float)cnt : 0.f;
        }
        if (t == 0) red[16] = 0.f;          // reg accumulator
        __syncthreads();

        if (t < NI) {
            float s = 0.f;
#pragma unroll
            for (int c = 0; c < CC; c++) { float m = sm[t*33 + c]; s = fmaf(m, m, s); }
            atomicAdd(&red[16], sqrtf(s));
        }

        float local = 0.f;
        for (int idx = t; idx < NI*NI; idx += TPB) {
            int i = idx / NI;
            int j = idx - i * NI;
            if (i != j) {
                float d2 = 0.f;
#pragma unroll
                for (int c = 0; c < CC; c++) {
                    float d = sm[i*33 + c] - sm[j*33 + c];
                    d2 = fmaf(d, d, d2);
                }
                float d = (d2 > 0.f) ? sqrtf(d2) : 1.f;   // jnp.where(d2>0, d2, 1)
                float h = fmaxf(4.f - d, 0.f);            // 2*DELTA_DIST
                local += h * h;
            }
        }
#pragma unroll
        for (int o = 16; o > 0; o >>= 1) local += __shfl_down_sync(0xffffffffu, local, o);
        if ((t & 31) == 0) red[t >> 5] = local;
        __syncthreads();
        if (t < 32) {
            float v = (t < TPB/32) ? red[t] : 0.f;
#pragma unroll
            for (int o = 16; o > 0; o >>= 1) v += __shfl_down_sync(0xffffffffu, v, o);
            if (t == 0) {
                g_dist[bb] = v;
                g_reg[bb]  = red[16];
            }
        }
    }
}

// -------- Pass 2: variance blocks + final combine (ticket) --------
__global__ __launch_bounds__(TPB) void pass2_k(const float* __restrict__ in,
                                               const int* __restrict__ tgt,
                                               float* __restrict__ out) {
    __shared__ float smean[CC*NI];  // [c*100+k]
    __shared__ float sinv[NI];
    __shared__ float red[TPB/32];
    __shared__ bool s_last;

    int blk = blockIdx.x;
    int b   = blk >> 7;
    int p0  = (blk & 127) * CHUNK;
    int t   = threadIdx.x;

    for (int i = t; i < CC*NI; i += TPB) smean[i] = g_means[(size_t)b*CC*NI + i];
    for (int i = t; i < NI;    i += TPB) sinv[i]  = g_invc[b*NI + i];
    __syncthreads();

    const int4* tg = (const int4*)(tgt + (size_t)b * PP + p0);
    int4 lv = tg[t];
    int lbl[4] = {lv.x, lv.y, lv.z, lv.w};

    float acc[4] = {0.f, 0.f, 0.f, 0.f};
    const float* base = in + (size_t)b * CC * PP + p0;
#pragma unroll 4
    for (int c = 0; c < CC; c++) {
        const float4* pc = (const float4*)(base + (size_t)c * PP);
        float4 v = pc[t];
        float d0 = v.x - smean[c*NI + lbl[0]];
        float d1 = v.y - smean[c*NI + lbl[1]];
        float d2 = v.z - smean[c*NI + lbl[2]];
        float d3 = v.w - smean[c*NI + lbl[3]];
        acc[0] = fmaf(d0, d0, acc[0]);
        acc[1] = fmaf(d1, d1, acc[1]);
        acc[2] = fmaf(d2, d2, acc[2]);
        acc[3] = fmaf(d3, d3, acc[3]);
    }

    float local = 0.f;
#pragma unroll
    for (int k = 0; k < 4; k++) {
        float n = sqrtf(acc[k]);
        float h = fmaxf(n - 0.75f, 0.f);   // DELTA_VAR
        local += h * h * sinv[lbl[k]];
    }
#pragma unroll
    for (int o = 16; o > 0; o >>= 1) local += __shfl_down_sync(0xffffffffu, local, o);
    if ((t & 31) == 0) red[t >> 5] = local;
    __syncthreads();
    if (t < 32) {
        float v = (t < TPB/32) ? red[t] : 0.f;
#pragma unroll
        for (int o = 16; o > 0; o >>= 1) v += __shfl_down_sync(0xffffffffu, v, o);
        if (t == 0) atomicAdd(&g_var[b], v);
    }

    // ---- ticket: last block -> final combine + cleanup for next replay ----
    __syncthreads();
    if (t == 0) {
        __threadfence();
        unsigned r = atomicAdd(&g_t2, 1u);
        s_last = (r == NBLK - 1);
    }
    __syncthreads();
    if (s_last) {
        if (t == 0) {
            float s = 0.f;
#pragma unroll
            for (int bb = 0; bb < BB; bb++) {
                float var_term  = g_var[bb]  * (1.f / (float)NI);
                float dist_term = g_dist[bb] * (1.f / (float)(NI * (NI - 1)));
                float reg_term  = g_reg[bb]  * (1.f / (float)NI);
                s += var_term + dist_term + 0.001f * reg_term;
            }
            out[0] = s * (1.f / (float)BB);
        }
        // cleanup for next replay (disjoint from t0's work above)
        for (int i = t; i < BB*CC*NI; i += TPB) g_sums[i] = 0.f;
        for (int i = t; i < BB*NI;    i += TPB) g_counts[i] = 0;
        __syncthreads();
        if (t < BB) g_var[t] = 0.f;
        if (t == 0) { g_t1 = 0u; g_t2 = 0u; }
    }
}

extern "C" void kernel_launch(void* const* d_in, const int* in_sizes, int n_in,
                              void* d_out, int out_size) {
    const float* in  = (const float*)d_in[0];
    const int*   tgt = (const int*)d_in[1];
    float*       out = (float*)d_out;
    (void)in_sizes; (void)n_in; (void)out_size;

    pass1_k<<<NBLK, TPB>>>(in, tgt);
    pass2_k<<<NBLK, TPB>>>(in, tgt, out);
}

// round 9
// speedup vs baseline: 1.5994x; 1.5994x over previous
#include <cuda_runtime.h>
#include <cuda_bf16.h>
#include <math.h>

// Problem constants (fixed by the reference setup)
#define BB 4
#define CC 32
#define NCP 16          // channel pairs
#define PP 262144       // 512*512 pixels per image
#define NI 100          // n_instances
#define CHUNK 2048      // pixels per block
#define TPB 512
#define NCOPY 8         // bank-sliced histogram copies
#define CHUNKS_PER_IMG (PP/CHUNK)   // 128
#define NBLK (BB*CHUNKS_PER_IMG)    // 512
#define NBLK2 (NBLK + BB)           // 516

// Scratch (no device allocation allowed -> __device__ globals).
// Zero at module load; pass2's ticket block re-zeros what needs zeroing after
// each run so every graph replay starts clean.
__device__ float g_sums[BB*CC*NI];   // [b][c][k]
__device__ int   g_counts[BB*NI];
__device__ float g_means[BB*CC*NI];  // [b][c*NI+k]  (overwritten every run)
__device__ float g_invc[BB*NI];      // (overwritten every run)
__device__ float g_var[BB];
__device__ float g_dist[BB];         // plain-stored every run
__device__ float g_reg[BB];          // plain-stored every run
__device__ unsigned int g_t1;
__device__ unsigned int g_t2;

// -------- Pass 1: per-label sums (bf16x2 atomics, 8-way bank-sliced) --------
// Ticket tail (last block) computes means + inv-counts only (cheap).
__global__ __launch_bounds__(TPB) void pass1_k(const float* __restrict__ in,
                                               const int* __restrict__ tgt) {
    __shared__ __nv_bfloat162 ssum[NCP*NI*NCOPY];   // [(cp*100+k)*8 + copy]
    __shared__ int scnt[NI];
    __shared__ bool s_last;

    int blk   = blockIdx.x;
    int b     = blk >> 7;           // /128
    int chunk = blk & 127;
    int p0    = chunk * CHUNK;
    int t     = threadIdx.x;
    int cpy   = t & (NCOPY-1);

    __nv_bfloat162 z2 = __nv_bfloat162(__float2bfloat16(0.f), __float2bfloat16(0.f));
    for (int i = t; i < NCP*NI*NCOPY; i += TPB) ssum[i] = z2;
    for (int i = t; i < NI;           i += TPB) scnt[i] = 0;
    __syncthreads();

    const int4* tg = (const int4*)(tgt + (size_t)b * PP + p0);
    int4 lv = tg[t];
    int lbl[4] = {lv.x, lv.y, lv.z, lv.w};
#pragma unroll
    for (int k = 0; k < 4; k++) atomicAdd(&scnt[lbl[k]], 1);

    int s0 = lbl[0]*NCOPY + cpy;
    int s1 = lbl[1]*NCOPY + cpy;
    int s2 = lbl[2]*NCOPY + cpy;
    int s3 = lbl[3]*NCOPY + cpy;

    const float* base = in + (size_t)b * CC * PP + p0;
#pragma unroll 2
    for (int cp = 0; cp < NCP; cp++) {
        const float4* pc0 = (const float4*)(base + (size_t)(2*cp)   * PP);
        const float4* pc1 = (const float4*)(base + (size_t)(2*cp+1) * PP);
        float4 v0 = pc0[t];
        float4 v1 = pc1[t];
        __nv_bfloat162 p0v = __floats2bfloat162_rn(v0.x, v1.x);
        __nv_bfloat162 p1v = __floats2bfloat162_rn(v0.y, v1.y);
        __nv_bfloat162 p2v = __floats2bfloat162_rn(v0.z, v1.z);
        __nv_bfloat162 p3v = __floats2bfloat162_rn(v0.w, v1.w);
        int cb = cp*NI*NCOPY;
        atomicAdd(&ssum[cb + s0], p0v);
        atomicAdd(&ssum[cb + s1], p1v);
        atomicAdd(&ssum[cb + s2], p2v);
        atomicAdd(&ssum[cb + s3], p3v);
    }
    __syncthreads();

    // flush: reduce copies, bf16 -> fp32 global accumulators
    float* gs = g_sums + (size_t)b * CC * NI;
    for (int i = t; i < NCP*NI; i += TPB) {
        int cp = i / NI;
        int k  = i - cp * NI;
        float sx = 0.f, sy = 0.f;
#pragma unroll
        for (int c = 0; c < NCOPY; c++) {
            __nv_bfloat162 v = ssum[i*NCOPY + c];
            sx += __bfloat162float(v.x);
            sy += __bfloat162float(v.y);
        }
        atomicAdd(&gs[(2*cp)   * NI + k], sx);
        atomicAdd(&gs[(2*cp+1) * NI + k], sy);
    }
    int* gc = g_counts + b * NI;
    for (int i = t; i < NI; i += TPB) atomicAdd(&gc[i], scnt[i]);

    // ---- ticket tail: means + inv-counts only (cheap, ~2us) ----
    __syncthreads();
    if (t == 0) {
        __threadfence();
        unsigned r = atomicAdd(&g_t1, 1u);
        s_last = (r == NBLK - 1);
    }
    __syncthreads();
    if (!s_last) return;

    for (int i = t; i < BB*CC*NI; i += TPB) {
        int bb = i / (CC*NI);
        int ck = i - bb * CC*NI;
        int k  = ck % NI;
        int cnt = g_counts[bb*NI + k];
        g_means[i] = (cnt > 0) ? g_sums[i] / (float)cnt : 0.f;
    }
    for (int i = t; i < BB*NI; i += TPB) {
        int cnt = g_counts[i];
        g_invc[i] = (cnt > 0) ? 1.f / (float)cnt : 0.f;
    }
}

// -------- Pass 2: 512 variance blocks + 4 distance/reg blocks + final --------
__global__ __launch_bounds__(TPB) void pass2_k(const float* __restrict__ in,
                                               const int* __restrict__ tgt,
                                               float* __restrict__ out) {
    __shared__ float sh[CC*NI + NI + 32];
    __shared__ bool s_last;
    int blk = blockIdx.x;
    int t   = threadIdx.x;

    if (blk < NBLK) {
        // ---- variance ----
        float* smean = sh;            // [c*100+k]
        float* sinv  = sh + CC*NI;
        float* red   = sh + CC*NI + NI;

        int b  = blk >> 7;
        int p0 = (blk & 127) * CHUNK;

        for (int i = t; i < CC*NI; i += TPB) smean[i] = g_means[(size_t)b*CC*NI + i];
        for (int i = t; i < NI;    i += TPB) sinv[i]  = g_invc[b*NI + i];
        __syncthreads();

        const int4* tg = (const int4*)(tgt + (size_t)b * PP + p0);
        int4 lv = tg[t];
        int lbl[4] = {lv.x, lv.y, lv.z, lv.w};

        float acc[4] = {0.f, 0.f, 0.f, 0.f};
        const float* base = in + (size_t)b * CC * PP + p0;
#pragma unroll 4
        for (int c = 0; c < CC; c++) {
            const float4* pc = (const float4*)(base + (size_t)c * PP);
            float4 v = pc[t];
            float d0 = v.x - smean[c*NI + lbl[0]];
            float d1 = v.y - smean[c*NI + lbl[1]];
            float d2 = v.z - smean[c*NI + lbl[2]];
            float d3 = v.w - smean[c*NI + lbl[3]];
            acc[0] = fmaf(d0, d0, acc[0]);
            acc[1] = fmaf(d1, d1, acc[1]);
            acc[2] = fmaf(d2, d2, acc[2]);
            acc[3] = fmaf(d3, d3, acc[3]);
        }

        float local = 0.f;
#pragma unroll
        for (int k = 0; k < 4; k++) {
            float n = sqrtf(acc[k]);
            float h = fmaxf(n - 0.75f, 0.f);   // DELTA_VAR
            local += h * h * sinv[lbl[k]];
        }
#pragma unroll
        for (int o = 16; o > 0; o >>= 1) local += __shfl_down_sync(0xffffffffu, local, o);
        if ((t & 31) == 0) red[t >> 5] = local;
        __syncthreads();
        if (t < 32) {
            float v = (t < TPB/32) ? red[t] : 0.f;
#pragma unroll
            for (int o = 16; o > 0; o >>= 1) v += __shfl_down_sync(0xffffffffu, v, o);
            if (t == 0) atomicAdd(&g_var[b], v);
        }
    } else {
        // ---- distance + reg for one batch (register-blocked) ----
        float* sm  = sh;              // [k*33+c] padded
        float* red = sh + NI*33;      // 16 partials + [16]=reg accum
        int bb = blk - NBLK;

        const float* gm = g_means + (size_t)bb * CC * NI;
        for (int i = t; i < CC*NI; i += TPB) {
            int c = i / NI;
            int k = i - c * NI;
            sm[k*33 + c] = gm[i];     // gm is [c*NI+k]
        }
        if (t == 0) red[16] = 0.f;
        __syncthreads();

        // reg term: threads 0..99
        if (t < NI) {
            float s = 0.f;
#pragma unroll
            for (int c = 0; c < CC; c++) { float m = sm[t*33 + c]; s = fmaf(m, m, s); }
            atomicAdd(&red[16], sqrtf(s));
        }

        // distance: group g owns i-range [g*20, g*20+20), thread owns column j
        int g = t / 100;              // 0..5
        int j = t - g * 100;          // 0..99
        float local = 0.f;
        if (g < 5) {
            float mj[CC];
#pragma unroll
            for (int c = 0; c < CC; c++) mj[c] = sm[j*33 + c];   // per-thread regs
            int i0 = g * 20;
            for (int i = i0; i < i0 + 20; i++) {
                float d2 = 0.f;
#pragma unroll
                for (int c = 0; c < CC; c++) {
                    float d = sm[i*33 + c] - mj[c];   // sm read is warp-broadcast
                    d2 = fmaf(d, d, d2);
                }
                if (i != j) {
                    float d = (d2 > 0.f) ? sqrtf(d2) : 1.f;   // jnp.where(d2>0,d2,1)
                    float h = fmaxf(4.f - d, 0.f);            // 2*DELTA_DIST
                    local += h * h;
                }
            }
        }
#pragma unroll
        for (int o = 16; o > 0; o >>= 1) local += __shfl_down_sync(0xffffffffu, local, o);
        if ((t & 31) == 0) red[t >> 5] = local;
        __syncthreads();
        if (t < 32) {
            float v = (t < TPB/32) ? red[t] : 0.f;
#pragma unroll
            for (int o = 16; o > 0; o >>= 1) v += __shfl_down_sync(0xffffffffu, v, o);
            if (t == 0) {
                g_dist[bb] = v;
                g_reg[bb]  = red[16];
            }
        }
    }

    // ---- ticket: last of all 516 blocks -> final combine + replay cleanup ----
    __syncthreads();
    if (t == 0) {
        __threadfence();
        unsigned r = atomicAdd(&g_t2, 1u);
        s_last = (r == NBLK2 - 1);
    }
    __syncthreads();
    if (s_last) {
        if (t == 0) {
            float s = 0.f;
#pragma unroll
            for (int bb = 0; bb < BB; bb++) {
                float var_term  = g_var[bb]  * (1.f / (float)NI);
                float dist_term = g_dist[bb] * (1.f / (float)(NI * (NI - 1)));
                float reg_term  = g_reg[bb]  * (1.f / (float)NI);
                s += var_term + dist_term + 0.001f * reg_term;
            }
            out[0] = s * (1.f / (float)BB);
        }
        // cleanup for next graph replay (disjoint from t0's work above)
        for (int i = t; i < BB*CC*NI; i += TPB) g_sums[i] = 0.f;
        for (int i = t; i < BB*NI;    i += TPB) g_counts[i] = 0;
        __syncthreads();
        if (t < BB) g_var[t] = 0.f;
        if (t == 0) { g_t1 = 0u; g_t2 = 0u; }
    }
}

extern "C" void kernel_launch(void* const* d_in, const int* in_sizes, int n_in,
                              void* d_out, int out_size) {
    const float* in  = (const float*)d_in[0];
    const int*   tgt = (const int*)d_in[1];
    float*       out = (float*)d_out;
    (void)in_sizes; (void)n_in; (void)out_size;

    pass1_k<<<NBLK, TPB>>>(in, tgt);
    pass2_k<<<NBLK2, TPB>>>(in, tgt, out);
}

// round 10
// speedup vs baseline: 1.6563x; 1.0356x over previous
#include <cuda_runtime.h>
#include <cuda_bf16.h>
#include <math.h>

// Problem constants (fixed by the reference setup)
#define BB 4
#define CC 32
#define NCP 16          // channel pairs
#define PP 262144       // 512*512 pixels per image
#define NI 100          // n_instances
#define CHUNK 2048      // pixels per block
#define TPB 512
#define NCOPY 8         // bank-sliced histogram copies
#define NBLK 512        // histogram/variance blocks (4 batches x 128 chunks)
#define NBLK2 516       // + 4 distance/reg blocks

// Scratch (no device allocation allowed -> __device__ globals).
// Zero at module load; the final ticket block re-zeros everything after each
// run so every graph replay starts clean.
__device__ float g_sums[BB*CC*NI];   // [b][c*NI+k]
__device__ int   g_counts[BB*NI];
__device__ float g_var[BB];
__device__ float g_dist[BB];
__device__ float g_reg[BB];
__device__ volatile unsigned int g_t1;   // phase-1 completion counter
__device__ unsigned int g_t2;            // kernel completion counter

// Single fused kernel. Grid = 516 blocks of 512 threads; smem 51.6KB and
// <=32 regs guarantee 4 blocks/SM -> all 516 blocks co-resident (capacity
// 148*4 = 592), making the device-side spin barrier safe.
__global__ __launch_bounds__(TPB, 4) void fused_k(const float* __restrict__ in,
                                                  const int* __restrict__ tgt,
                                                  float* __restrict__ out) {
    __shared__ __nv_bfloat162 ssum[NCP*NI*NCOPY];   // 51.2KB; reused as float[] later
    __shared__ int scnt[NI];
    __shared__ float sred[24];                      // [0:16) warp partials, [16] reg accum
    __shared__ bool s_last;

    int blk = blockIdx.x;
    int t   = threadIdx.x;
    int b, p0 = 0;
    int lbl[4] = {0, 0, 0, 0};

    if (blk < NBLK) {
        // ================= Phase 1: per-label sums (bf16x2, 8-way sliced) ======
        b  = blk >> 7;
        p0 = (blk & 127) * CHUNK;
        int cpy = t & (NCOPY-1);

        __nv_bfloat162 z2 = __nv_bfloat162(__float2bfloat16(0.f), __float2bfloat16(0.f));
        for (int i = t; i < NCP*NI*NCOPY; i += TPB) ssum[i] = z2;
        for (int i = t; i < NI;           i += TPB) scnt[i] = 0;
        __syncthreads();

        const int4* tg = (const int4*)(tgt + (size_t)b * PP + p0);
        int4 lv = tg[t];
        lbl[0] = lv.x; lbl[1] = lv.y; lbl[2] = lv.z; lbl[3] = lv.w;
#pragma unroll
        for (int k = 0; k < 4; k++) atomicAdd(&scnt[lbl[k]], 1);

        int s0 = lbl[0]*NCOPY + cpy;
        int s1 = lbl[1]*NCOPY + cpy;
        int s2 = lbl[2]*NCOPY + cpy;
        int s3 = lbl[3]*NCOPY + cpy;

        const float* base = in + (size_t)b * CC * PP + p0;
#pragma unroll 2
        for (int cp = 0; cp < NCP; cp++) {
            const float4* pc0 = (const float4*)(base + (size_t)(2*cp)   * PP);
            const float4* pc1 = (const float4*)(base + (size_t)(2*cp+1) * PP);
            float4 v0 = pc0[t];
            float4 v1 = pc1[t];
            __nv_bfloat162 p0v = __floats2bfloat162_rn(v0.x, v1.x);
            __nv_bfloat162 p1v = __floats2bfloat162_rn(v0.y, v1.y);
            __nv_bfloat162 p2v = __floats2bfloat162_rn(v0.z, v1.z);
            __nv_bfloat162 p3v = __floats2bfloat162_rn(v0.w, v1.w);
            int cb = cp*NI*NCOPY;
            atomicAdd(&ssum[cb + s0], p0v);
            atomicAdd(&ssum[cb + s1], p1v);
            atomicAdd(&ssum[cb + s2], p2v);
            atomicAdd(&ssum[cb + s3], p3v);
        }
        __syncthreads();

        // flush partials -> fp32 global accumulators
        float* gs = g_sums + (size_t)b * CC * NI;
        for (int i = t; i < NCP*NI; i += TPB) {
            int cp = i / NI;
            int k  = i - cp * NI;
            float sx = 0.f, sy = 0.f;
#pragma unroll
            for (int c = 0; c < NCOPY; c++) {
                __nv_bfloat162 v = ssum[i*NCOPY + c];
                sx += __bfloat162float(v.x);
                sy += __bfloat162float(v.y);
            }
            atomicAdd(&gs[(2*cp)   * NI + k], sx);
            atomicAdd(&gs[(2*cp+1) * NI + k], sy);
        }
        int* gc = g_counts + b * NI;
        for (int i = t; i < NI; i += TPB) atomicAdd(&gc[i], scnt[i]);
    } else {
        b = blk - NBLK;   // distance blocks: one batch each
    }

    // ================= Grid barrier: wait for all 512 flushes ==================
    __syncthreads();
    if (t == 0) {
        if (blk < NBLK) {
            __threadfence();                      // release g_sums/g_counts
            atomicAdd((unsigned int*)&g_t1, 1u);
        }
        while (g_t1 < NBLK) { }                   // volatile poll (L2)
        __threadfence();                          // acquire
    }
    __syncthreads();

    if (blk < NBLK) {
        // ================= Phase 2: variance term ==============================
        float* smean = (float*)ssum;              // [c*NI+k], 3200 floats
        float* sinv  = smean + CC*NI;             // [k]
        const float* gs = g_sums + (size_t)b * CC * NI;
        const int*   gc = g_counts + b * NI;
        for (int i = t; i < CC*NI; i += TPB) {
            int k = i % NI;
            int cnt = gc[k];
            smean[i] = (cnt > 0) ? gs[i] / (float)cnt : 0.f;
        }
        for (int i = t; i < NI; i += TPB) {
            int cnt = gc[i];
            sinv[i] = (cnt > 0) ? 1.f / (float)cnt : 0.f;
        }
        __syncthreads();

        float acc[4] = {0.f, 0.f, 0.f, 0.f};
        const float* base = in + (size_t)b * CC * PP + p0;
#pragma unroll 4
        for (int c = 0; c < CC; c++) {
            const float4* pc = (const float4*)(base + (size_t)c * PP);
            float4 v = pc[t];
            float d0 = v.x - smean[c*NI + lbl[0]];
            float d1 = v.y - smean[c*NI + lbl[1]];
            float d2 = v.z - smean[c*NI + lbl[2]];
            float d3 = v.w - smean[c*NI + lbl[3]];
            acc[0] = fmaf(d0, d0, acc[0]);
            acc[1] = fmaf(d1, d1, acc[1]);
            acc[2] = fmaf(d2, d2, acc[2]);
            acc[3] = fmaf(d3, d3, acc[3]);
        }

        float local = 0.f;
#pragma unroll
        for (int k = 0; k < 4; k++) {
            float n = sqrtf(acc[k]);
            float h = fmaxf(n - 0.75f, 0.f);       // DELTA_VAR
            local += h * h * sinv[lbl[k]];
        }
#pragma unroll
        for (int o = 16; o > 0; o >>= 1) local += __shfl_down_sync(0xffffffffu, local, o);
        if ((t & 31) == 0) sred[t >> 5] = local;
        __syncthreads();
        if (t < 32) {
            float v = (t < TPB/32) ? sred[t] : 0.f;
#pragma unroll
            for (int o = 16; o > 0; o >>= 1) v += __shfl_down_sync(0xffffffffu, v, o);
            if (t == 0) atomicAdd(&g_var[b], v);
        }
    } else {
        // ================= Distance + reg terms (one batch per block) ==========
        float* sm = (float*)ssum;                  // [k*33+c] padded
        const float* gs = g_sums + (size_t)b * CC * NI;
        const int*   gc = g_counts + b * NI;
        for (int i = t; i < CC*NI; i += TPB) {
            int c = i / NI;
            int k = i - c * NI;
            int cnt = gc[k];
            sm[k*33 + c] = (cnt > 0) ? gs[i] / (float)cnt : 0.f;
        }
        if (t == 0) sred[16] = 0.f;
        __syncthreads();

        // reg term
        if (t < NI) {
            float s = 0.f;
#pragma unroll
            for (int c = 0; c < CC; c++) { float m = sm[t*33 + c]; s = fmaf(m, m, s); }
            atomicAdd(&sred[16], sqrtf(s));
        }

        // distance term (strided pairs, smem-only: keeps regs low)
        float local = 0.f;
        for (int idx = t; idx < NI*NI; idx += TPB) {
            int i = idx / NI;
            int j = idx - i * NI;
            if (i != j) {
                float d2 = 0.f;
#pragma unroll
                for (int c = 0; c < CC; c++) {
                    float d = sm[i*33 + c] - sm[j*33 + c];
                    d2 = fmaf(d, d, d2);
                }
                float d = (d2 > 0.f) ? sqrtf(d2) : 1.f;   // jnp.where(d2>0, d2, 1)
                float h = fmaxf(4.f - d, 0.f);            // 2*DELTA_DIST
                local += h * h;
            }
        }
#pragma unroll
        for (int o = 16; o > 0; o >>= 1) local += __shfl_down_sync(0xffffffffu, local, o);
        if ((t & 31) == 0) sred[t >> 5] = local;
        __syncthreads();
        if (t < 32) {
            float v = (t < TPB/32) ? sred[t] : 0.f;
#pragma unroll
            for (int o = 16; o > 0; o >>= 1) v += __shfl_down_sync(0xffffffffu, v, o);
            if (t == 0) {
                g_dist[b] = v;
                g_reg[b]  = sred[16];
            }
        }
    }

    // ================= Final ticket: combine + cleanup for next replay =========
    __syncthreads();
    if (t == 0) {
        __threadfence();
        unsigned r = atomicAdd(&g_t2, 1u);
        s_last = (r == NBLK2 - 1);
    }
    __syncthreads();
    if (s_last) {
        if (t == 0) {
            float s = 0.f;
#pragma unroll
            for (int bb = 0; bb < BB; bb++) {
                float var_term  = g_var[bb]  * (1.f / (float)NI);
                float dist_term = g_dist[bb] * (1.f / (float)(NI * (NI - 1)));
                float reg_term  = g_reg[bb]  * (1.f / (float)NI);
                s += var_term + dist_term + 0.001f * reg_term;
            }
            out[0] = s * (1.f / (float)BB);
        }
        // cleanup for next graph replay (disjoint from t0's work above)
        for (int i = t; i < BB*CC*NI; i += TPB) g_sums[i] = 0.f;
        for (int i = t; i < BB*NI;    i += TPB) g_counts[i] = 0;
        __syncthreads();
        if (t < BB) g_var[t] = 0.f;
        if (t == 0) { g_t2 = 0u; __threadfence(); g_t1 = 0u; }
    }
}

extern "C" void kernel_launch(void* const* d_in, const int* in_sizes, int n_in,
                              void* d_out, int out_size) {
    const float* in  = (const float*)d_in[0];
    const int*   tgt = (const int*)d_in[1];
    float*       out = (float*)d_out;
    (void)in_sizes; (void)n_in; (void)out_size;

    fused_k<<<NBLK2, TPB>>>(in, tgt, out);
}

// round 11
// speedup vs baseline: 1.7113x; 1.0332x over previous
#include <cuda_runtime.h>
#include <cuda_bf16.h>
#include <math.h>

// Problem constants (fixed by the reference setup)
#define BB 4
#define CC 32
#define NCP 16          // channel pairs
#define PP 262144       // 512*512 pixels per image
#define NI 100          // n_instances
#define CHUNK 2048      // pixels per block
#define TPB 512
#define NCOPY 8         // bank-sliced histogram copies
#define NBLK 512        // 4 batches x 128 chunks
#define NBLK2 516       // + 4 distance/reg blocks

// Scratch (no device allocation allowed -> __device__ globals).
// Zero at module load; pass2's ticket block re-zeros accumulators after each
// run so every graph replay starts clean. g_means/g_invc/g_dist/g_reg are
// overwritten (not accumulated) every run.
__device__ float g_sums[BB*CC*NI];   // [b][c*NI+k]
__device__ int   g_counts[BB*NI];
__device__ float g_means[BB*CC*NI];
__device__ float g_invc[BB*NI];
__device__ float g_var[BB];
__device__ float g_dist[BB];
__device__ float g_reg[BB];
__device__ unsigned int g_t2;

// -------- Pass 1: per-label sums (bf16x2 atomics, 8-way bank-sliced) --------
__global__ __launch_bounds__(TPB) void pass1_k(const float* __restrict__ in,
                                               const int* __restrict__ tgt) {
    __shared__ __nv_bfloat162 ssum[NCP*NI*NCOPY];   // [(cp*100+k)*8 + copy]
    __shared__ int scnt[NI];

    int blk   = blockIdx.x;
    int b     = blk >> 7;           // /128
    int chunk = blk & 127;
    int p0    = chunk * CHUNK;
    int t     = threadIdx.x;
    int cpy   = t & (NCOPY-1);

    __nv_bfloat162 z2 = __nv_bfloat162(__float2bfloat16(0.f), __float2bfloat16(0.f));
    for (int i = t; i < NCP*NI*NCOPY; i += TPB) ssum[i] = z2;
    for (int i = t; i < NI;           i += TPB) scnt[i] = 0;
    __syncthreads();

    const int4* tg = (const int4*)(tgt + (size_t)b * PP + p0);
    int4 lv = tg[t];
    int lbl[4] = {lv.x, lv.y, lv.z, lv.w};
#pragma unroll
    for (int k = 0; k < 4; k++) atomicAdd(&scnt[lbl[k]], 1);

    int s0 = lbl[0]*NCOPY + cpy;
    int s1 = lbl[1]*NCOPY + cpy;
    int s2 = lbl[2]*NCOPY + cpy;
    int s3 = lbl[3]*NCOPY + cpy;

    const float* base = in + (size_t)b * CC * PP + p0;
#pragma unroll 2
    for (int cp = 0; cp < NCP; cp++) {
        const float4* pc0 = (const float4*)(base + (size_t)(2*cp)   * PP);
        const float4* pc1 = (const float4*)(base + (size_t)(2*cp+1) * PP);
        float4 v0 = pc0[t];
        float4 v1 = pc1[t];
        __nv_bfloat162 p0v = __floats2bfloat162_rn(v0.x, v1.x);
        __nv_bfloat162 p1v = __floats2bfloat162_rn(v0.y, v1.y);
        __nv_bfloat162 p2v = __floats2bfloat162_rn(v0.z, v1.z);
        __nv_bfloat162 p3v = __floats2bfloat162_rn(v0.w, v1.w);
        int cb = cp*NI*NCOPY;
        atomicAdd(&ssum[cb + s0], p0v);
        atomicAdd(&ssum[cb + s1], p1v);
        atomicAdd(&ssum[cb + s2], p2v);
        atomicAdd(&ssum[cb + s3], p3v);
    }
    __syncthreads();

    // flush: reduce copies, bf16 -> fp32 global accumulators
    float* gs = g_sums + (size_t)b * CC * NI;
    for (int i = t; i < NCP*NI; i += TPB) {
        int cp = i / NI;
        int k  = i - cp * NI;
        float sx = 0.f, sy = 0.f;
#pragma unroll
        for (int c = 0; c < NCOPY; c++) {
            __nv_bfloat162 v = ssum[i*NCOPY + c];
            sx += __bfloat162float(v.x);
            sy += __bfloat162float(v.y);
        }
        atomicAdd(&gs[(2*cp)   * NI + k], sx);
        atomicAdd(&gs[(2*cp+1) * NI + k], sy);
    }
    int* gc = g_counts + b * NI;
    for (int i = t; i < NI; i += TPB) atomicAdd(&gc[i], scnt[i]);
}

// -------- Means: tiny parallel kernel (one block per batch) --------
__global__ __launch_bounds__(256) void means_k() {
    int b = blockIdx.x;
    int t = threadIdx.x;
    const float* gs = g_sums + (size_t)b * CC * NI;
    const int*   gc = g_counts + b * NI;
    for (int i = t; i < CC*NI; i += 256) {
        int k = i % NI;
        int cnt = gc[k];
        g_means[(size_t)b*CC*NI + i] = (cnt > 0) ? gs[i] / (float)cnt : 0.f;
    }
    for (int k = t; k < NI; k += 256) {
        int cnt = gc[k];
        g_invc[b*NI + k] = (cnt > 0) ? 1.f / (float)cnt : 0.f;
    }
}

// -------- Pass 2: 512 variance blocks + 4 distance/reg blocks + final --------
__global__ __launch_bounds__(TPB) void pass2_k(const float* __restrict__ in,
                                               const int* __restrict__ tgt,
                                               float* __restrict__ out) {
    __shared__ float sh[NI*33 + 32];   // union: variance smean+sinv | distance sm
    __shared__ bool s_last;
    int blk = blockIdx.x;
    int t   = threadIdx.x;

    if (blk < NBLK) {
        // ---- variance ----
        float* smean = sh;             // [c*100+k], 3200
        float* sinv  = sh + CC*NI;     // [k], 100
        float* red   = sh + CC*NI + NI;

        int b  = blk >> 7;
        int p0 = (blk & 127) * CHUNK;

        for (int i = t; i < CC*NI; i += TPB) smean[i] = g_means[(size_t)b*CC*NI + i];
        for (int i = t; i < NI;    i += TPB) sinv[i]  = g_invc[b*NI + i];
        __syncthreads();

        const int4* tg = (const int4*)(tgt + (size_t)b * PP + p0);
        int4 lv = tg[t];
        int lbl[4] = {lv.x, lv.y, lv.z, lv.w};

        float acc[4] = {0.f, 0.f, 0.f, 0.f};
        const float* base = in + (size_t)b * CC * PP + p0;
#pragma unroll 4
        for (int c = 0; c < CC; c++) {
            const float4* pc = (const float4*)(base + (size_t)c * PP);
            float4 v = pc[t];
            float d0 = v.x - smean[c*NI + lbl[0]];
            float d1 = v.y - smean[c*NI + lbl[1]];
            float d2 = v.z - smean[c*NI + lbl[2]];
            float d3 = v.w - smean[c*NI + lbl[3]];
            acc[0] = fmaf(d0, d0, acc[0]);
            acc[1] = fmaf(d1, d1, acc[1]);
            acc[2] = fmaf(d2, d2, acc[2]);
            acc[3] = fmaf(d3, d3, acc[3]);
        }

        float local = 0.f;
#pragma unroll
        for (int k = 0; k < 4; k++) {
            float n = sqrtf(acc[k]);
            float h = fmaxf(n - 0.75f, 0.f);   // DELTA_VAR
            local += h * h * sinv[lbl[k]];
        }
#pragma unroll
        for (int o = 16; o > 0; o >>= 1) local += __shfl_down_sync(0xffffffffu, local, o);
        if ((t & 31) == 0) red[t >> 5] = local;
        __syncthreads();
        if (t < 32) {
            float v = (t < TPB/32) ? red[t] : 0.f;
#pragma unroll
            for (int o = 16; o > 0; o >>= 1) v += __shfl_down_sync(0xffffffffu, v, o);
            if (t == 0) atomicAdd(&g_var[b], v);
        }
    } else {
        // ---- distance + reg for one batch (smem-only, keeps regs low) ----
        float* sm  = sh;               // [k*33+c] padded
        float* red = sh + NI*33;       // [0:16) partials, [16] reg accum
        int b = blk - NBLK;

        const float* gm = g_means + (size_t)b * CC * NI;   // [c*NI+k]
        for (int i = t; i < CC*NI; i += TPB) {
            int c = i / NI;
            int k = i - c * NI;
            sm[k*33 + c] = gm[i];
        }
        if (t == 0) red[16] = 0.f;
        __syncthreads();

        // reg term
        if (t < NI) {
            float s = 0.f;
#pragma unroll
            for (int c = 0; c < CC; c++) { float m = sm[t*33 + c]; s = fmaf(m, m, s); }
            atomicAdd(&red[16], sqrtf(s));
        }

        // distance term (strided pairs)
        float local = 0.f;
        for (int idx = t; idx < NI*NI; idx += TPB) {
            int i = idx / NI;
            int j = idx - i * NI;
            if (i != j) {
                float d2 = 0.f;
#pragma unroll
                for (int c = 0; c < CC; c++) {
                    float d = sm[i*33 + c] - sm[j*33 + c];
                    d2 = fmaf(d, d, d2);
                }
                float d = (d2 > 0.f) ? sqrtf(d2) : 1.f;   // jnp.where(d2>0, d2, 1)
                float h = fmaxf(4.f - d, 0.f);            // 2*DELTA_DIST
                local += h * h;
            }
        }
#pragma unroll
        for (int o = 16; o > 0; o >>= 1) local += __shfl_down_sync(0xffffffffu, local, o);
        if ((t & 31) == 0) red[t >> 5] = local;
        __syncthreads();
        if (t < 32) {
            float v = (t < TPB/32) ? red[t] : 0.f;
#pragma unroll
            for (int o = 16; o > 0; o >>= 1) v += __shfl_down_sync(0xffffffffu, v, o);
            if (t == 0) {
                g_dist[b] = v;
                g_reg[b]  = red[16];
            }
        }
    }

    // ---- ticket: last of 516 blocks -> final combine + replay cleanup ----
    __syncthreads();
    if (t == 0) {
        __threadfence();
        unsigned r = atomicAdd(&g_t2, 1u);
        s_last = (r == NBLK2 - 1);
    }
    __syncthreads();
    if (s_last) {
        if (t == 0) {
            float s = 0.f;
#pragma unroll
            for (int bb = 0; bb < BB; bb++) {
                float var_term  = g_var[bb]  * (1.f / (float)NI);
                float dist_term = g_dist[bb] * (1.f / (float)(NI * (NI - 1)));
                float reg_term  = g_reg[bb]  * (1.f / (float)NI);
                s += var_term + dist_term + 0.001f * reg_term;
            }
            out[0] = s * (1.f / (float)BB);
        }
        // cleanup for next graph replay (disjoint from t0's work above)
        for (int i = t; i < BB*CC*NI; i += TPB) g_sums[i] = 0.f;
        for (int i = t; i < BB*NI;    i += TPB) g_counts[i] = 0;
        __syncthreads();
        if (t < BB) g_var[t] = 0.f;
        if (t == 0) g_t2 = 0u;
    }
}

extern "C" void kernel_launch(void* const* d_in, const int* in_sizes, int n_in,
                              void* d_out, int out_size) {
    const float* in  = (const float*)d_in[0];
    const int*   tgt = (const int*)d_in[1];
    float*       out = (float*)d_out;
    (void)in_sizes; (void)n_in; (void)out_size;

    pass1_k<<<NBLK, TPB>>>(in, tgt);
    means_k<<<BB, 256>>>();
    pass2_k<<<NBLK2, TPB>>>(in, tgt, out);
}